// round 9
// baseline (speedup 1.0000x reference)
#include <cuda_runtime.h>
#include <cstdint>

// Shapes (fixed): b=4096, d=1024, u=32, r=32, n_obs=25
#define B_DIM 4096
#define D_DIM 1024
#define U_DIM 32
#define OBS_DIM 25

// ---------------------------------------------------------------------------
// Device scratch
// ---------------------------------------------------------------------------
__device__ float g_ut_dt[B_DIM * U_DIM];   // ut*dt                          [b, u]
__device__ float g_WqT[D_DIM * D_DIM];     // WqT[n=(m*32+r)][j] = N_Q[m,j,r]
__device__ float g_WpT[D_DIM * D_DIM];     // WpT[i][c=(m*32+r)] = N_P[m,i,r]
__device__ float g_S[B_DIM * D_DIM];       // S[b, m*32+r]

// ---------------------------------------------------------------------------
// Prep kernels
// ---------------------------------------------------------------------------
__global__ void prep_ut_dt(const float* __restrict__ ut, const float* __restrict__ dt) {
    int idx = blockIdx.x * 256 + threadIdx.x;
    if (idx < B_DIM * U_DIM) g_ut_dt[idx] = ut[idx] * dt[0];
}

// g_WqT[(m*32+r)*1024 + j] = NQ[m*32768 + j*32 + r]
__global__ void prep_wqT(const float* __restrict__ NQ) {
    __shared__ float t[32][33];
    int m = blockIdx.y;
    int j0 = blockIdx.x * 32;
    t[threadIdx.y][threadIdx.x] = NQ[m * 32768 + (j0 + threadIdx.y) * 32 + threadIdx.x];
    __syncthreads();
    g_WqT[(m * 32 + threadIdx.y) * D_DIM + j0 + threadIdx.x] = t[threadIdx.x][threadIdx.y];
}

// g_WpT[i*1024 + m*32 + r] = NP[m*32768 + i*32 + r]
__global__ void prep_wpT(const float* __restrict__ NP) {
    int idx = blockIdx.x * 256 + threadIdx.x;   // 1M
    int i = idx >> 10;
    int c = idx & 1023;
    int m = c >> 5;
    int r = c & 31;
    g_WpT[idx] = NP[m * 32768 + i * 32 + r];
}

// ---------------------------------------------------------------------------
// mma.sync tf32 building blocks
// ---------------------------------------------------------------------------
__device__ __forceinline__ uint32_t f2tf32(float x) {
    uint32_t r;
    asm("cvt.rna.tf32.f32 %0, %1;" : "=r"(r) : "f"(x));
    return r;
}
__device__ __forceinline__ uint32_t smem_u32(const void* p) {
    uint32_t a;
    asm("{ .reg .u64 t; cvta.to.shared.u64 t, %1; cvt.u32.u64 %0, t; }" : "=r"(a) : "l"(p));
    return a;
}
__device__ __forceinline__ void mma_tf32(float (&c)[4], const uint32_t (&a)[4],
                                         const uint32_t (&b)[2]) {
    asm volatile(
        "mma.sync.aligned.m16n8k8.row.col.f32.tf32.tf32.f32 "
        "{%0,%1,%2,%3}, {%4,%5,%6,%7}, {%8,%9}, {%0,%1,%2,%3};"
        : "+f"(c[0]), "+f"(c[1]), "+f"(c[2]), "+f"(c[3])
        : "r"(a[0]), "r"(a[1]), "r"(a[2]), "r"(a[3]), "r"(b[0]), "r"(b[1]));
}
__device__ __forceinline__ void ldsm4(uint32_t (&r)[4], uint32_t a) {
    asm volatile("ldmatrix.sync.aligned.m8n8.x4.shared.b16 {%0,%1,%2,%3}, [%4];"
                 : "=r"(r[0]), "=r"(r[1]), "=r"(r[2]), "=r"(r[3]) : "r"(a));
}
__device__ __forceinline__ uint4 cvt4(float4 v) {
    uint4 u = { f2tf32(v.x), f2tf32(v.y), f2tf32(v.z), f2tf32(v.w) };
    return u;
}

// ---------------------------------------------------------------------------
// GEMM: CTA tile 128x256, BK=32, 512 threads = 16 warps (4m x 4n of 32x64).
// Smem rows: [row][32 floats] = 128B, 16B-unit col swizzled by (c16 ^ (row&7)).
// Double buffered: A 2x16KB, B 2x32KB = 96KB dynamic.
// ---------------------------------------------------------------------------
#define A_BYTES 16384
#define B_BYTES 32768
#define SMEM_NEED (2 * (A_BYTES + B_BYTES))
#define NTHREADS 512

__device__ __forceinline__ void chunk_src_1(int c, const float* z, int brow, int bcol,
                                            const float*& a, int& alda,
                                            const float*& b, int& bldb) {
    a = z + brow * D_DIM + c * 32;      alda = D_DIM;
    b = g_WqT + bcol * D_DIM + c * 32;  bldb = D_DIM;
}
__device__ __forceinline__ void chunk_src_2(int c, const float* z, const float* Ab,
                                            const float* Bb, int brow, int bcol,
                                            const float*& a, int& alda,
                                            const float*& b, int& bldb) {
    if (c < 32)      { a = z + brow * D_DIM + c * 32;          alda = D_DIM;
                       b = Ab + bcol * D_DIM + c * 32;         bldb = D_DIM; }
    else if (c < 64) { a = g_S + brow * D_DIM + (c - 32) * 32; alda = D_DIM;
                       b = g_WpT + bcol * D_DIM + (c - 32) * 32; bldb = D_DIM; }
    else             { a = g_ut_dt + brow * U_DIM;             alda = U_DIM;
                       b = Bb + bcol * U_DIM;                  bldb = U_DIM; }
}

// 3 units/thread: unit 0 -> A (512 quarter-rows), units 1-2 -> B (1024 quarter-rows)
__device__ __forceinline__ void load_units(const float* __restrict__ a, int alda,
                                           const float* __restrict__ b, int bldb,
                                           float4 (&st)[3][2]) {
    const int t = threadIdx.x;
    {
        const float* p = a + (t >> 2) * alda + (t & 3) * 8;
        st[0][0] = *(const float4*)(p);
        st[0][1] = *(const float4*)(p + 4);
    }
#pragma unroll
    for (int i = 1; i < 3; ++i) {
        int j = t + (i - 1) * NTHREADS;
        const float* p = b + (j >> 2) * bldb + (j & 3) * 8;
        st[i][0] = *(const float4*)(p);
        st[i][1] = *(const float4*)(p + 4);
    }
}

__device__ __forceinline__ void store_units(const float4 (&st)[3][2], char* Ab, char* Bb) {
    const int t = threadIdx.x;
#pragma unroll
    for (int i = 0; i < 3; ++i) {
        int row, q;
        char* base;
        if (i == 0) { row = t >> 2; q = t & 3; base = Ab; }
        else        { int j = t + (i - 1) * NTHREADS; row = j >> 2; q = j & 3; base = Bb; }
        float* rp = (float*)(base + row * 128);
        int c0 = (2 * q) ^ (row & 7);
        int c1 = (2 * q + 1) ^ (row & 7);
        *(uint4*)(rp + c0 * 4) = cvt4(st[i][0]);
        *(uint4*)(rp + c1 * 4) = cvt4(st[i][1]);
    }
}

__device__ __forceinline__ void compute_chunk(uint32_t abase, uint32_t bbase,
                                              float (&acc)[2][8][4],
                                              int m0, int n0, int lane) {
    const int e3 = lane & 7;
    const int rA = e3 + ((lane >> 3) & 1) * 8;
    const int hA = lane >> 4;
    const int rB = e3 + ((lane >> 4) & 1) * 8;
    const int hB = (lane >> 3) & 1;
#pragma unroll
    for (int k8 = 0; k8 < 4; ++k8) {
        const int c16b = 2 * k8;
        uint32_t afr[2][4];
#pragma unroll
        for (int mt = 0; mt < 2; ++mt) {
            uint32_t addr = abase + (uint32_t)((m0 + mt * 16 + rA) * 128 +
                                               (((c16b + hA) ^ e3) << 4));
            ldsm4(afr[mt], addr);
        }
        uint32_t bfr[8][2];
#pragma unroll
        for (int p = 0; p < 4; ++p) {
            uint32_t tmp[4];
            uint32_t addr = bbase + (uint32_t)((n0 + p * 16 + rB) * 128 +
                                               (((c16b + hB) ^ e3) << 4));
            ldsm4(tmp, addr);
            bfr[2 * p][0] = tmp[0]; bfr[2 * p][1] = tmp[1];
            bfr[2 * p + 1][0] = tmp[2]; bfr[2 * p + 1][1] = tmp[3];
        }
#pragma unroll
        for (int mt = 0; mt < 2; ++mt)
#pragma unroll
            for (int nt = 0; nt < 8; ++nt)
                mma_tf32(acc[mt][nt], afr[mt], bfr[nt]);
    }
}

template <int MODE>   // 1: GEMM1 (C=32 -> g_S scaled); 2: GEMM2 (C=65 -> out)
__global__ void __launch_bounds__(NTHREADS, 1) gemm_mma(
    const float* __restrict__ z,
    const float* __restrict__ Ab,
    const float* __restrict__ Bb,
    float* __restrict__ outp)
{
    extern __shared__ char dsm[];
    char* Asm[2] = { dsm, dsm + A_BYTES };
    char* Bsm[2] = { dsm + 2 * A_BYTES, dsm + 2 * A_BYTES + B_BYTES };
    const uint32_t sb = smem_u32(dsm);
    const uint32_t aoff[2] = { sb, sb + A_BYTES };
    const uint32_t boff[2] = { sb + 2 * A_BYTES, sb + 2 * A_BYTES + B_BYTES };

    const int t = threadIdx.x;
    const int lane = t & 31;
    const int w = t >> 5;                 // 0..15
    const int m0 = (w >> 2) * 32;         // 4 m-groups of 32
    const int n0 = (w & 3) * 64;          // 4 n-groups of 64
    const int brow = blockIdx.y * 128;
    const int bcol = blockIdx.x * 256;
    const int C = (MODE == 1) ? 32 : 65;

    float acc[2][8][4];
#pragma unroll
    for (int mt = 0; mt < 2; ++mt)
#pragma unroll
        for (int nt = 0; nt < 8; ++nt)
#pragma unroll
            for (int i = 0; i < 4; ++i) acc[mt][nt][i] = 0.f;

    float4 st[3][2];
    const float *a, *b;
    int alda, bldb;

    if (MODE == 1) chunk_src_1(0, z, brow, bcol, a, alda, b, bldb);
    else           chunk_src_2(0, z, Ab, Bb, brow, bcol, a, alda, b, bldb);
    load_units(a, alda, b, bldb, st);
    store_units(st, Asm[0], Bsm[0]);
    __syncthreads();

    int buf = 0;
    for (int c = 0; c < C; ++c) {
        const bool more = (c + 1 < C);
        if (more) {
            if (MODE == 1) chunk_src_1(c + 1, z, brow, bcol, a, alda, b, bldb);
            else           chunk_src_2(c + 1, z, Ab, Bb, brow, bcol, a, alda, b, bldb);
            load_units(a, alda, b, bldb, st);
        }
        compute_chunk(aoff[buf], boff[buf], acc, m0, n0, lane);
        if (more) store_units(st, Asm[buf ^ 1], Bsm[buf ^ 1]);
        __syncthreads();
        buf ^= 1;
    }

    // Epilogue (m16n8 C layout: lane -> rows {r, r+8}, col pair 2*(lane&3))
    const int r = lane >> 2;
    const int cp = (lane & 3) * 2;
#pragma unroll
    for (int mt = 0; mt < 2; ++mt) {
        const int row0 = brow + m0 + mt * 16 + r;
        const int row1 = row0 + 8;
#pragma unroll
        for (int nt = 0; nt < 8; ++nt) {
            const int colbase = bcol + n0 + nt * 8;
            const int col = colbase + cp;
            if (MODE == 1) {
                const int g = colbase >> 5;
                const float s0 = g_ut_dt[row0 * U_DIM + g];
                const float s1 = g_ut_dt[row1 * U_DIM + g];
                float2 v0 = { acc[mt][nt][0] * s0, acc[mt][nt][1] * s0 };
                float2 v1 = { acc[mt][nt][2] * s1, acc[mt][nt][3] * s1 };
                *(float2*)&g_S[row0 * D_DIM + col] = v0;
                *(float2*)&g_S[row1 * D_DIM + col] = v1;
            } else {
                float2 v0 = { acc[mt][nt][0], acc[mt][nt][1] };
                float2 v1 = { acc[mt][nt][2], acc[mt][nt][3] };
                *(float2*)&outp[row0 * D_DIM + col] = v0;
                *(float2*)&outp[row1 * D_DIM + col] = v1;
            }
        }
    }
}

// ---------------------------------------------------------------------------
// yt = Z @ C^T + ut_dt @ D^T  (exact fp32)
// ---------------------------------------------------------------------------
__global__ void __launch_bounds__(128) yt_kernel(const float* __restrict__ Z,
                                                 const float* __restrict__ C,
                                                 const float* __restrict__ Dm,
                                                 float* __restrict__ yt)
{
    __shared__ float Cs[OBS_DIM][132];
    const int lane = threadIdx.x & 31;
    const int warp = threadIdx.x >> 5;
    const int b = blockIdx.x * 4 + warp;

    float acc[OBS_DIM];
    {
        float ud = g_ut_dt[b * U_DIM + lane];
#pragma unroll
        for (int o = 0; o < OBS_DIM; ++o) acc[o] = ud * Dm[o * U_DIM + lane];
    }
    for (int kt = 0; kt < D_DIM; kt += 128) {
        __syncthreads();
        for (int idx = threadIdx.x; idx < OBS_DIM * 128; idx += 128) {
            int o = idx >> 7, kk = idx & 127;
            Cs[o][kk] = C[o * D_DIM + kt + kk];
        }
        __syncthreads();
        float4 zv = *(const float4*)(Z + b * D_DIM + kt + lane * 4);
#pragma unroll
        for (int o = 0; o < OBS_DIM; ++o) {
            float4 cv = *(const float4*)&Cs[o][lane * 4];
            acc[o] += zv.x * cv.x + zv.y * cv.y + zv.z * cv.z + zv.w * cv.w;
        }
    }
#pragma unroll
    for (int o = 0; o < OBS_DIM; ++o) {
#pragma unroll
        for (int off = 16; off; off >>= 1)
            acc[o] += __shfl_xor_sync(0xffffffffu, acc[o], off);
    }
    if (lane == 0) {
#pragma unroll
        for (int o = 0; o < OBS_DIM; ++o) yt[b * OBS_DIM + o] = acc[o];
    }
}

// ---------------------------------------------------------------------------
// Launch
// ---------------------------------------------------------------------------
extern "C" void kernel_launch(void* const* d_in, const int* in_sizes, int n_in,
                              void* d_out, int out_size) {
    const float* z_dyn = (const float*)d_in[0];
    // d_in[1] = z_static (unused)
    const float* dt = (const float*)d_in[2];
    const float* ut = (const float*)d_in[3];
    const float* A = (const float*)d_in[4];
    const float* Bb = (const float*)d_in[5];
    const float* NP = (const float*)d_in[6];
    const float* NQ = (const float*)d_in[7];
    const float* C = (const float*)d_in[8];
    const float* Dm = (const float*)d_in[9];
    float* out = (float*)d_out;

    cudaFuncSetAttribute(gemm_mma<1>, cudaFuncAttributeMaxDynamicSharedMemorySize, SMEM_NEED);
    cudaFuncSetAttribute(gemm_mma<2>, cudaFuncAttributeMaxDynamicSharedMemorySize, SMEM_NEED);

    prep_ut_dt<<<(B_DIM * U_DIM + 255) / 256, 256>>>(ut, dt);
    prep_wqT<<<dim3(D_DIM / 32, U_DIM), dim3(32, 32)>>>(NQ);
    prep_wpT<<<(D_DIM * D_DIM) / 256, 256>>>(NP);

    dim3 grid(D_DIM / 256, B_DIM / 128);   // (4, 32) = 128 CTAs
    gemm_mma<1><<<grid, NTHREADS, SMEM_NEED>>>(z_dyn, A, Bb, out);
    gemm_mma<2><<<grid, NTHREADS, SMEM_NEED>>>(z_dyn, A, Bb, out);

    yt_kernel<<<B_DIM / 4, 128>>>(out, C, Dm, out + B_DIM * D_DIM);
}

// round 11
// speedup vs baseline: 1.0872x; 1.0872x over previous
#include <cuda_runtime.h>
#include <cstdint>

// Shapes (fixed): b=4096, d=1024, u=32, r=32, n_obs=25
#define B_DIM 4096
#define D_DIM 1024
#define U_DIM 32
#define OBS_DIM 25

// ---------------------------------------------------------------------------
// Device scratch (all GEMM operands pre-rounded to tf32 so cp.async staging
// reads the exact same values the old cvt-at-staging path produced)
// ---------------------------------------------------------------------------
__device__ float g_ut_dt[B_DIM * U_DIM];   // ut*dt, FULL fp32 (epilogue scales)
__device__ float g_utc[B_DIM * U_DIM];     // tf32-rounded ut*dt (GEMM operand)
__device__ float g_Zc[B_DIM * D_DIM];      // tf32-rounded z_dyn
__device__ float g_Ac[D_DIM * D_DIM];      // tf32-rounded A_bilinear       [N,K]
__device__ float g_Bc[D_DIM * U_DIM];      // tf32-rounded B_bilinear       [N,K]
__device__ float g_WqT[D_DIM * D_DIM];     // tf32  WqT[(m*32+r)][j] = N_Q[m,j,r]
__device__ float g_WpT[D_DIM * D_DIM];     // tf32  WpT[i][(m*32+r)] = N_P[m,i,r]
__device__ float g_S[B_DIM * D_DIM];       // tf32-rounded S[b, m*32+r]

// ---------------------------------------------------------------------------
// Helpers
// ---------------------------------------------------------------------------
__device__ __forceinline__ uint32_t f2tf32(float x) {
    uint32_t r;
    asm("cvt.rna.tf32.f32 %0, %1;" : "=r"(r) : "f"(x));
    return r;
}
__device__ __forceinline__ float tf32v(float x) { return __uint_as_float(f2tf32(x)); }
__device__ __forceinline__ uint32_t smem_u32(const void* p) {
    uint32_t a;
    asm("{ .reg .u64 t; cvta.to.shared.u64 t, %1; cvt.u32.u64 %0, t; }" : "=r"(a) : "l"(p));
    return a;
}
__device__ __forceinline__ void mma_tf32(float (&c)[4], const uint32_t (&a)[4],
                                         const uint32_t (&b)[2]) {
    asm volatile(
        "mma.sync.aligned.m16n8k8.row.col.f32.tf32.tf32.f32 "
        "{%0,%1,%2,%3}, {%4,%5,%6,%7}, {%8,%9}, {%0,%1,%2,%3};"
        : "+f"(c[0]), "+f"(c[1]), "+f"(c[2]), "+f"(c[3])
        : "r"(a[0]), "r"(a[1]), "r"(a[2]), "r"(a[3]), "r"(b[0]), "r"(b[1]));
}
__device__ __forceinline__ void ldsm4(uint32_t (&r)[4], uint32_t a) {
    asm volatile("ldmatrix.sync.aligned.m8n8.x4.shared.b16 {%0,%1,%2,%3}, [%4];"
                 : "=r"(r[0]), "=r"(r[1]), "=r"(r[2]), "=r"(r[3]) : "r"(a));
}
__device__ __forceinline__ void cp16(uint32_t dst, const void* src) {
    asm volatile("cp.async.cg.shared.global [%0], [%1], 16;" :: "r"(dst), "l"(src));
}
#define CP_COMMIT() asm volatile("cp.async.commit_group;" ::: "memory")
#define CP_WAIT1()  asm volatile("cp.async.wait_group 1;" ::: "memory")

// ---------------------------------------------------------------------------
// Prep kernels (tf32 rounding folded in)
// ---------------------------------------------------------------------------
__global__ void prep_ut_dt(const float* __restrict__ ut, const float* __restrict__ dt) {
    int idx = blockIdx.x * 256 + threadIdx.x;
    if (idx < B_DIM * U_DIM) {
        float v = ut[idx] * dt[0];
        g_ut_dt[idx] = v;
        g_utc[idx] = tf32v(v);
    }
}
__global__ void cvt_arr(const float* __restrict__ in, float* __restrict__ out, int n) {
    int idx = blockIdx.x * 256 + threadIdx.x;
    if (idx < n) out[idx] = tf32v(in[idx]);
}
__global__ void prep_wqT(const float* __restrict__ NQ) {
    __shared__ float t[32][33];
    int m = blockIdx.y;
    int j0 = blockIdx.x * 32;
    t[threadIdx.y][threadIdx.x] = NQ[m * 32768 + (j0 + threadIdx.y) * 32 + threadIdx.x];
    __syncthreads();
    g_WqT[(m * 32 + threadIdx.y) * D_DIM + j0 + threadIdx.x] = tf32v(t[threadIdx.x][threadIdx.y]);
}
__global__ void prep_wpT(const float* __restrict__ NP) {
    int idx = blockIdx.x * 256 + threadIdx.x;   // 1M
    int i = idx >> 10;
    int c = idx & 1023;
    int m = c >> 5;
    int r = c & 31;
    g_WpT[idx] = tf32v(NP[m * 32768 + i * 32 + r]);
}

// ---------------------------------------------------------------------------
// GEMM: CTA 128x256, BK=32, 512 threads = 16 warps (4m x 4n of 32x64 tiles).
// Smem row = 128B (32 floats), 16B-unit col swizzle (c16 ^ (row&7)).
// 3-stage cp.async pipeline: A 3x16KB + B 3x32KB = 144KB dynamic smem.
// ---------------------------------------------------------------------------
#define A_BYTES 16384
#define B_BYTES 32768
#define STAGE_BYTES (A_BYTES + B_BYTES)
#define SMEM_NEED (3 * STAGE_BYTES)
#define NTHREADS 512

__device__ __forceinline__ void chunk_src_1(int c, int brow, int bcol,
                                            const float*& a, int& alda,
                                            const float*& b, int& bldb) {
    a = g_Zc + brow * D_DIM + c * 32;   alda = D_DIM;
    b = g_WqT + bcol * D_DIM + c * 32;  bldb = D_DIM;
}
__device__ __forceinline__ void chunk_src_2(int c, int brow, int bcol,
                                            const float*& a, int& alda,
                                            const float*& b, int& bldb) {
    if (c < 32)      { a = g_Zc + brow * D_DIM + c * 32;         alda = D_DIM;
                       b = g_Ac + bcol * D_DIM + c * 32;         bldb = D_DIM; }
    else if (c < 64) { a = g_S + brow * D_DIM + (c - 32) * 32;   alda = D_DIM;
                       b = g_WpT + bcol * D_DIM + (c - 32) * 32; bldb = D_DIM; }
    else             { a = g_utc + brow * U_DIM;                 alda = U_DIM;
                       b = g_Bc + bcol * U_DIM;                  bldb = U_DIM; }
}

// Issue cp.async for one stage: 6x16B per thread (A:2, B:4)
__device__ __forceinline__ void issue_stage(const float* __restrict__ a, int alda,
                                            const float* __restrict__ b, int bldb,
                                            uint32_t abase, uint32_t bbase) {
    const int t = threadIdx.x;
    {   // A: unit u = t, row 0..127, quarter q
        int row = t >> 2, q = t & 3;
        const float* p = a + row * alda + q * 8;
        uint32_t rp = abase + row * 128;
        cp16(rp + (((2 * q) ^ (row & 7)) << 4), p);
        cp16(rp + (((2 * q + 1) ^ (row & 7)) << 4), p + 4);
    }
#pragma unroll
    for (int i = 0; i < 2; ++i) {   // B: units t, t+512 -> rows 0..255
        int j = t + i * NTHREADS;
        int row = j >> 2, q = j & 3;
        const float* p = b + row * bldb + q * 8;
        uint32_t rp = bbase + row * 128;
        cp16(rp + (((2 * q) ^ (row & 7)) << 4), p);
        cp16(rp + (((2 * q + 1) ^ (row & 7)) << 4), p + 4);
    }
}

__device__ __forceinline__ void compute_chunk(uint32_t abase, uint32_t bbase,
                                              float (&acc)[2][8][4],
                                              int m0, int n0, int lane) {
    const int e3 = lane & 7;
    const int rA = e3 + ((lane >> 3) & 1) * 8;
    const int hA = lane >> 4;
    const int rB = e3 + ((lane >> 4) & 1) * 8;
    const int hB = (lane >> 3) & 1;
#pragma unroll
    for (int k8 = 0; k8 < 4; ++k8) {
        const int c16b = 2 * k8;
        uint32_t afr[2][4];
#pragma unroll
        for (int mt = 0; mt < 2; ++mt) {
            uint32_t addr = abase + (uint32_t)((m0 + mt * 16 + rA) * 128 +
                                               (((c16b + hA) ^ e3) << 4));
            ldsm4(afr[mt], addr);
        }
        uint32_t bfr[8][2];
#pragma unroll
        for (int p = 0; p < 4; ++p) {
            uint32_t tmp[4];
            uint32_t addr = bbase + (uint32_t)((n0 + p * 16 + rB) * 128 +
                                               (((c16b + hB) ^ e3) << 4));
            ldsm4(tmp, addr);
            bfr[2 * p][0] = tmp[0]; bfr[2 * p][1] = tmp[1];
            bfr[2 * p + 1][0] = tmp[2]; bfr[2 * p + 1][1] = tmp[3];
        }
#pragma unroll
        for (int mt = 0; mt < 2; ++mt)
#pragma unroll
            for (int nt = 0; nt < 8; ++nt)
                mma_tf32(acc[mt][nt], afr[mt], bfr[nt]);
    }
}

template <int MODE>   // 1: GEMM1 (C=32 -> g_S scaled+rounded); 2: GEMM2 (C=65 -> out)
__global__ void __launch_bounds__(NTHREADS, 1) gemm_mma(float* __restrict__ outp)
{
    extern __shared__ char dsm[];
    const uint32_t sb = smem_u32(dsm);
    uint32_t aoff[3], boff[3];
#pragma unroll
    for (int s = 0; s < 3; ++s) {
        aoff[s] = sb + s * STAGE_BYTES;
        boff[s] = sb + s * STAGE_BYTES + A_BYTES;
    }

    const int t = threadIdx.x;
    const int lane = t & 31;
    const int w = t >> 5;
    const int m0 = (w >> 2) * 32;
    const int n0 = (w & 3) * 64;
    const int brow = blockIdx.y * 128;
    const int bcol = blockIdx.x * 256;
    const int C = (MODE == 1) ? 32 : 65;

    float acc[2][8][4];
#pragma unroll
    for (int mt = 0; mt < 2; ++mt)
#pragma unroll
        for (int nt = 0; nt < 8; ++nt)
#pragma unroll
            for (int i = 0; i < 4; ++i) acc[mt][nt][i] = 0.f;

    const float *a, *b;
    int alda, bldb;

    // prologue: stages 0,1
#pragma unroll
    for (int s = 0; s < 2; ++s) {
        if (MODE == 1) chunk_src_1(s, brow, bcol, a, alda, b, bldb);
        else           chunk_src_2(s, brow, bcol, a, alda, b, bldb);
        issue_stage(a, alda, b, bldb, aoff[s], boff[s]);
        CP_COMMIT();
    }

    int buf = 0;
    for (int c = 0; c < C; ++c) {
        CP_WAIT1();            // stage c complete (only c+1 may remain in flight)
        __syncthreads();       // data visible; all warps done reading buf (c-1)%3
        if (c + 2 < C) {       // issue stage c+2 into buffer (c+2)%3 = (c-1)%3
            if (MODE == 1) chunk_src_1(c + 2, brow, bcol, a, alda, b, bldb);
            else           chunk_src_2(c + 2, brow, bcol, a, alda, b, bldb);
            int s = (c + 2) % 3;
            issue_stage(a, alda, b, bldb, aoff[s], boff[s]);
        }
        CP_COMMIT();           // always commit to keep group accounting aligned
        compute_chunk(aoff[buf], boff[buf], acc, m0, n0, lane);
        buf = (buf + 1) % 3;
    }

    // Epilogue (m16n8 C layout: lane -> rows {r, r+8}, col pair 2*(lane&3))
    const int r = lane >> 2;
    const int cp = (lane & 3) * 2;
#pragma unroll
    for (int mt = 0; mt < 2; ++mt) {
        const int row0 = brow + m0 + mt * 16 + r;
        const int row1 = row0 + 8;
#pragma unroll
        for (int nt = 0; nt < 8; ++nt) {
            const int colbase = bcol + n0 + nt * 8;
            const int col = colbase + cp;
            if (MODE == 1) {
                const int g = colbase >> 5;
                const float s0 = g_ut_dt[row0 * U_DIM + g];
                const float s1 = g_ut_dt[row1 * U_DIM + g];
                // store tf32-rounded (matches old cvt-at-staging numerics)
                float2 v0 = { tf32v(acc[mt][nt][0] * s0), tf32v(acc[mt][nt][1] * s0) };
                float2 v1 = { tf32v(acc[mt][nt][2] * s1), tf32v(acc[mt][nt][3] * s1) };
                *(float2*)&g_S[row0 * D_DIM + col] = v0;
                *(float2*)&g_S[row1 * D_DIM + col] = v1;
            } else {
                float2 v0 = { acc[mt][nt][0], acc[mt][nt][1] };
                float2 v1 = { acc[mt][nt][2], acc[mt][nt][3] };
                *(float2*)&outp[row0 * D_DIM + col] = v0;
                *(float2*)&outp[row1 * D_DIM + col] = v1;
            }
        }
    }
}

// ---------------------------------------------------------------------------
// yt = Z @ C^T + ut_dt @ D^T  (exact fp32)
// ---------------------------------------------------------------------------
__global__ void __launch_bounds__(128) yt_kernel(const float* __restrict__ Z,
                                                 const float* __restrict__ C,
                                                 const float* __restrict__ Dm,
                                                 float* __restrict__ yt)
{
    __shared__ float Cs[OBS_DIM][132];
    const int lane = threadIdx.x & 31;
    const int warp = threadIdx.x >> 5;
    const int b = blockIdx.x * 4 + warp;

    float acc[OBS_DIM];
    {
        float ud = g_ut_dt[b * U_DIM + lane];
#pragma unroll
        for (int o = 0; o < OBS_DIM; ++o) acc[o] = ud * Dm[o * U_DIM + lane];
    }
    for (int kt = 0; kt < D_DIM; kt += 128) {
        __syncthreads();
        for (int idx = threadIdx.x; idx < OBS_DIM * 128; idx += 128) {
            int o = idx >> 7, kk = idx & 127;
            Cs[o][kk] = C[o * D_DIM + kt + kk];
        }
        __syncthreads();
        float4 zv = *(const float4*)(Z + b * D_DIM + kt + lane * 4);
#pragma unroll
        for (int o = 0; o < OBS_DIM; ++o) {
            float4 cv = *(const float4*)&Cs[o][lane * 4];
            acc[o] += zv.x * cv.x + zv.y * cv.y + zv.z * cv.z + zv.w * cv.w;
        }
    }
#pragma unroll
    for (int o = 0; o < OBS_DIM; ++o) {
#pragma unroll
        for (int off = 16; off; off >>= 1)
            acc[o] += __shfl_xor_sync(0xffffffffu, acc[o], off);
    }
    if (lane == 0) {
#pragma unroll
        for (int o = 0; o < OBS_DIM; ++o) yt[b * OBS_DIM + o] = acc[o];
    }
}

// ---------------------------------------------------------------------------
// Launch
// ---------------------------------------------------------------------------
extern "C" void kernel_launch(void* const* d_in, const int* in_sizes, int n_in,
                              void* d_out, int out_size) {
    const float* z_dyn = (const float*)d_in[0];
    // d_in[1] = z_static (unused)
    const float* dt = (const float*)d_in[2];
    const float* ut = (const float*)d_in[3];
    const float* A = (const float*)d_in[4];
    const float* Bb = (const float*)d_in[5];
    const float* NP = (const float*)d_in[6];
    const float* NQ = (const float*)d_in[7];
    const float* C = (const float*)d_in[8];
    const float* Dm = (const float*)d_in[9];
    float* out = (float*)d_out;

    cudaFuncSetAttribute(gemm_mma<1>, cudaFuncAttributeMaxDynamicSharedMemorySize, SMEM_NEED);
    cudaFuncSetAttribute(gemm_mma<2>, cudaFuncAttributeMaxDynamicSharedMemorySize, SMEM_NEED);

    float* zc; float* ac; float* bc;
    cudaGetSymbolAddress((void**)&zc, g_Zc);
    cudaGetSymbolAddress((void**)&ac, g_Ac);
    cudaGetSymbolAddress((void**)&bc, g_Bc);

    prep_ut_dt<<<(B_DIM * U_DIM + 255) / 256, 256>>>(ut, dt);
    cvt_arr<<<(B_DIM * D_DIM + 255) / 256, 256>>>(z_dyn, zc, B_DIM * D_DIM);
    cvt_arr<<<(D_DIM * D_DIM + 255) / 256, 256>>>(A, ac, D_DIM * D_DIM);
    cvt_arr<<<(D_DIM * U_DIM + 255) / 256, 256>>>(Bb, bc, D_DIM * U_DIM);
    prep_wqT<<<dim3(D_DIM / 32, U_DIM), dim3(32, 32)>>>(NQ);
    prep_wpT<<<(D_DIM * D_DIM) / 256, 256>>>(NP);

    dim3 grid(D_DIM / 256, B_DIM / 128);   // (4, 32) = 128 CTAs
    gemm_mma<1><<<grid, NTHREADS, SMEM_NEED>>>(out);
    gemm_mma<2><<<grid, NTHREADS, SMEM_NEED>>>(out);

    yt_kernel<<<B_DIM / 4, 128>>>(out, C, Dm, out + B_DIM * D_DIM);
}